// round 7
// baseline (speedup 1.0000x reference)
#include <cuda_runtime.h>
#include <cuda_bf16.h>
#include <cstdint>

// ============================================================================
// out[65536,256] = (x[65536,512] @ W[256,512]^T) * 0.125 + 0.1*bias
// bf16 hi/lo 3-term split + mma.sync.m16n8k16 (base sm_103, no tcgen05).
// R7: A path = LDG->register convert->STS bf16 (no fp32 smem round trip).
// Triple-buffered A (STS) and B (cp.async); ONE syncthreads per stage.
// Crossbar model: 128KB/CTA-stage vs 168KB before => tensor ~77% ceiling.
// ============================================================================

#define KD 512
#define ND 256
#define MROWS 65536
#define BM 128
#define BN 128
#define KB 32                 // k-cols per stage
#define NS 16                 // KD / KB
#define THREADS 256

#define AT_BYTES 16384        // A stage: hi 8KB + lo 8KB
#define BT_BYTES 16384        // B stage: hi 8KB + lo 8KB
#define A_BASE 0u
#define B_BASE (3u * AT_BYTES)                 // 49152
#define SMEM_TOTAL (3 * AT_BYTES + 3 * BT_BYTES)   // 98304 -> 2 CTAs/SM

// ---- pre-split W tiles: [stage 16][row 256][32 bf16 = 64B], SW64 swizzled ----
__device__ __align__(1024) unsigned char g_whi[16 * 16384];
__device__ __align__(1024) unsigned char g_wlo[16 * 16384];

__device__ __forceinline__ uint32_t swz64(uint32_t o) {
    return o ^ ((o >> 3) & 0x30);
}
__device__ __forceinline__ uint32_t smem_u32(const void* p) {
    uint32_t a;
    asm("{ .reg .u64 t; cvta.to.shared.u64 t, %1; cvt.u32.u64 %0, t; }"
        : "=r"(a) : "l"(p));
    return a;
}
__device__ __forceinline__ void cp16(uint32_t saddr, const void* gptr) {
    asm volatile("cp.async.cg.shared.global [%0], [%1], 16;\n"
                 :: "r"(saddr), "l"(gptr));
}
#define CP_COMMIT() asm volatile("cp.async.commit_group;\n" ::: "memory")

__device__ __forceinline__ void sts128(uint32_t a, uint32_t r0, uint32_t r1,
                                       uint32_t r2, uint32_t r3) {
    asm volatile("st.shared.v4.b32 [%0], {%1,%2,%3,%4};"
                 :: "r"(a), "r"(r0), "r"(r1), "r"(r2), "r"(r3) : "memory");
}
// pack (lo arg -> low half, hi arg -> high half) as bf16x2
__device__ __forceinline__ uint32_t packbf(float lo, float hi) {
    uint32_t r;
    asm("cvt.rn.bf16x2.f32 %0, %1, %2;" : "=r"(r) : "f"(hi), "f"(lo));
    return r;
}

#define LDSM4(r, addr) \
    asm volatile("ldmatrix.sync.aligned.m8n8.x4.shared.b16 {%0,%1,%2,%3}, [%4];" \
                 : "=r"((r)[0]), "=r"((r)[1]), "=r"((r)[2]), "=r"((r)[3])  \
                 : "r"(addr))

#define MMA(d, a, b0, b1) \
    asm volatile("mma.sync.aligned.m16n8k16.row.col.f32.bf16.bf16.f32 " \
                 "{%0,%1,%2,%3}, {%4,%5,%6,%7}, {%8,%9}, {%0,%1,%2,%3};" \
                 : "+f"((d)[0]), "+f"((d)[1]), "+f"((d)[2]), "+f"((d)[3]) \
                 : "r"((a)[0]), "r"((a)[1]), "r"((a)[2]), "r"((a)[3]),    \
                   "r"(b0), "r"(b1))

// ============================================================================
// W split: fp32 -> bf16 hi/lo, tile layout [stage][row][64B] with SW64.
// ============================================================================
__global__ void split_w_kernel(const float* __restrict__ src) {
    const int n4 = ND * KD / 4;                       // 32768
    int i = blockIdx.x * blockDim.x + threadIdx.x;
    if (i >= n4) return;
    float4 v = ((const float4*)src)[i];
    int r = i >> 7;                // W row (n index)
    int c4 = i & 127;
    int s = c4 >> 3;               // k-stage
    int cc = c4 & 7;
    size_t tile = (size_t)s * 16384;
    uint32_t off = swz64((uint32_t)(r * 64 + cc * 8));

    uint32_t h01 = packbf(v.x, v.y);
    uint32_t h23 = packbf(v.z, v.w);
    float lx = v.x - __uint_as_float(h01 << 16);
    float ly = v.y - __uint_as_float(h01 & 0xFFFF0000u);
    float lz = v.z - __uint_as_float(h23 << 16);
    float lw = v.w - __uint_as_float(h23 & 0xFFFF0000u);
    *(uint2*)(g_whi + tile + off) = make_uint2(h01, h23);
    *(uint2*)(g_wlo + tile + off) = make_uint2(packbf(lx, ly), packbf(lz, lw));
}

// ============================================================================
// Fused GEMM
// ============================================================================
// B stage copy: 512 x 16B hi + 512 x 16B lo; 2 of each per thread.
__device__ __forceinline__ void issue_b(uint32_t sb, int t, int buf, int bn,
                                        int tid) {
    const uint32_t bb = sb + B_BASE + (uint32_t)buf * BT_BYTES;
    const size_t g = (size_t)t * 16384 + (size_t)bn * 8192;
#pragma unroll
    for (int j = 0; j < 2; j++) {
        const uint32_t o = (uint32_t)(tid + 256 * j) * 16;
        cp16(bb + o, g_whi + g + o);
        cp16(bb + 8192 + o, g_wlo + g + o);
    }
    CP_COMMIT();
}

// A prefetch: 2 units/thread; unit = (row r, 32B chunk c) -> 8 fp32
__device__ __forceinline__ void load_pf(float4 pf[2][2], const float* x,
                                        int t, int bm, int tid) {
#pragma unroll
    for (int j = 0; j < 2; j++) {
        const int idx = tid + 256 * j;
        const int r = idx >> 2;
        const int c = idx & 3;
        const float* src = x + (size_t)(bm + r) * KD + t * KB + c * 8;
        pf[j][0] = *(const float4*)(src);
        pf[j][1] = *(const float4*)(src + 4);
    }
}

// convert prefetched fp32 -> bf16 hi/lo tiles in smem buffer `buf`
__device__ __forceinline__ void convert_sts(uint32_t sb, int buf,
                                            const float4 pf[2][2], int tid) {
    const uint32_t ab = sb + A_BASE + (uint32_t)buf * AT_BYTES;
#pragma unroll
    for (int j = 0; j < 2; j++) {
        const int idx = tid + 256 * j;
        const int r = idx >> 2;
        const int c = idx & 3;
        const uint32_t daddr = swz64((uint32_t)(r * 64 + c * 16));
        float4 v0 = pf[j][0], v1 = pf[j][1];
        uint32_t h0 = packbf(v0.x, v0.y);
        uint32_t h1 = packbf(v0.z, v0.w);
        uint32_t h2 = packbf(v1.x, v1.y);
        uint32_t h3 = packbf(v1.z, v1.w);
        sts128(ab + daddr, h0, h1, h2, h3);
        uint32_t l0 = packbf(v0.x - __uint_as_float(h0 << 16),
                             v0.y - __uint_as_float(h0 & 0xFFFF0000u));
        uint32_t l1 = packbf(v0.z - __uint_as_float(h1 << 16),
                             v0.w - __uint_as_float(h1 & 0xFFFF0000u));
        uint32_t l2 = packbf(v1.x - __uint_as_float(h2 << 16),
                             v1.y - __uint_as_float(h2 & 0xFFFF0000u));
        uint32_t l3 = packbf(v1.z - __uint_as_float(h3 << 16),
                             v1.w - __uint_as_float(h3 & 0xFFFF0000u));
        sts128(ab + 8192 + daddr, l0, l1, l2, l3);
    }
}

__global__ void __launch_bounds__(THREADS, 2)
gemm_fused_kernel(const float* __restrict__ x, const float* __restrict__ bias,
                  float* __restrict__ out) {
    extern __shared__ __align__(1024) char smem[];
    const uint32_t sb = smem_u32(smem);
    const int tid = threadIdx.x;
    const int wid = tid >> 5;
    const int lane = tid & 31;
    const int wm = wid >> 2;       // 0..1, warp rows wm*64
    const int wn = wid & 3;        // 0..3, warp cols wn*32
    const int bn = blockIdx.x;     // fastest: bn pair co-resident (x L2 reuse)
    const int bm = blockIdx.y * BM;

    // ---- prologue ----
    float4 pf[2][2];
    load_pf(pf, x, 0, bm, tid);    // A stage 0 -> regs
    issue_b(sb, 0, 0, bn, tid);    // B group 0
    issue_b(sb, 1, 1, bn, tid);    // B group 1
    convert_sts(sb, 0, pf, tid);   // A stage 0 -> smem buf 0
    load_pf(pf, x, 1, bm, tid);    // A stage 1 -> regs

    // per-lane ldmatrix constants
    const int lrow8 = ((lane >> 3) & 1) * 8 + (lane & 7);
    const int lk16 = (lane >> 4) * 16;
    uint32_t aoff[4], boff[2];
#pragma unroll
    for (int mi = 0; mi < 4; mi++)
        aoff[mi] = (uint32_t)((wm * 64 + mi * 16 + lrow8) * 64 + lk16);
#pragma unroll
    for (int g = 0; g < 2; g++)
        boff[g] = (uint32_t)((wn * 32 + g * 16 + lrow8) * 64 + lk16);

    float acc[4][4][4];
#pragma unroll
    for (int mi = 0; mi < 4; mi++)
#pragma unroll
        for (int ni = 0; ni < 4; ni++)
#pragma unroll
            for (int j = 0; j < 4; j++) acc[mi][ni][j] = 0.0f;

    int cur = 0;                   // s % 3
#pragma unroll 1
    for (int s = 0; s < NS; s++) {
        // B(s) arrived (pending <= 1 newer group), barrier makes it CTA-visible
        if (s == NS - 1)
            asm volatile("cp.async.wait_group 0;\n" ::: "memory");
        else
            asm volatile("cp.async.wait_group 1;\n" ::: "memory");
        __syncthreads();           // also: everyone done LDSM of stage s-1

        // producers for future stages
        const int nxt = (cur == 2) ? 0 : cur + 1;
        if (s + 2 < NS) issue_b(sb, s + 2, (nxt == 2) ? 0 : nxt + 1, bn, tid);
        if (s + 1 < NS) convert_sts(sb, nxt, pf, tid);
        if (s + 2 < NS) load_pf(pf, x, s + 2, bm, tid);

        // ---- consumer: all-ldmatrix + MMA on stage s (buffer cur) ----
        const uint32_t ahi = sb + A_BASE + (uint32_t)cur * AT_BYTES;
        const uint32_t alo = ahi + 8192;
        const uint32_t bhi = sb + B_BASE + (uint32_t)cur * BT_BYTES;
        const uint32_t blo = bhi + 8192;

#pragma unroll
        for (int ks = 0; ks < 2; ks++) {
            const uint32_t kadd = (uint32_t)(ks * 32);
            uint32_t bht[2][4], blt[2][4];
#pragma unroll
            for (int g = 0; g < 2; g++) {
                LDSM4(bht[g], bhi + swz64(boff[g] + kadd));
                LDSM4(blt[g], blo + swz64(boff[g] + kadd));
            }
#pragma unroll
            for (int mi = 0; mi < 4; mi++) {
                uint32_t ah[4], al[4];
                LDSM4(ah, ahi + swz64(aoff[mi] + kadd));
                LDSM4(al, alo + swz64(aoff[mi] + kadd));
#pragma unroll
                for (int g = 0; g < 2; g++) {
                    MMA(acc[mi][2 * g],     ah, bht[g][0], bht[g][2]);
                    MMA(acc[mi][2 * g + 1], ah, bht[g][1], bht[g][3]);
                    MMA(acc[mi][2 * g],     ah, blt[g][0], blt[g][2]);
                    MMA(acc[mi][2 * g + 1], ah, blt[g][1], blt[g][3]);
                    MMA(acc[mi][2 * g],     al, bht[g][0], bht[g][2]);
                    MMA(acc[mi][2 * g + 1], al, bht[g][1], bht[g][3]);
                }
            }
        }
        cur = nxt;
    }

    // ---- epilogue ----
    const int quad = lane >> 2;
    const int tq = lane & 3;
    const float scale = 0.125f;
#pragma unroll
    for (int mi = 0; mi < 4; mi++) {
        const int row0 = bm + wm * 64 + mi * 16 + quad;
#pragma unroll
        for (int ni = 0; ni < 4; ni++) {
            const int col = bn * BN + wn * 32 + ni * 8 + tq * 2;
            const float2 bv = *(const float2*)(bias + col);
            float2 o0, o1;
            o0.x = acc[mi][ni][0] * scale + 0.1f * bv.x;
            o0.y = acc[mi][ni][1] * scale + 0.1f * bv.y;
            o1.x = acc[mi][ni][2] * scale + 0.1f * bv.x;
            o1.y = acc[mi][ni][3] * scale + 0.1f * bv.y;
            *(float2*)(out + (size_t)row0 * ND + col) = o0;
            *(float2*)(out + (size_t)(row0 + 8) * ND + col) = o1;
        }
    }
}

// ============================================================================
extern "C" void kernel_launch(void* const* d_in, const int* in_sizes, int n_in,
                              void* d_out, int out_size) {
    const float* x      = (const float*)d_in[0];   // [65536, 512]
    const float* weight = (const float*)d_in[1];   // [256, 512]
    const float* bias   = (const float*)d_in[2];   // [256]
    float* out = (float*)d_out;                    // [65536, 256]

    cudaFuncSetAttribute(gemm_fused_kernel,
                         cudaFuncAttributeMaxDynamicSharedMemorySize, SMEM_TOTAL);

    split_w_kernel<<<128, 256>>>(weight);
    dim3 grid(ND / BN, MROWS / BM);   // (2, 512), bn fastest
    gemm_fused_kernel<<<grid, THREADS, SMEM_TOTAL>>>(x, bias, out);
}

// round 10
// speedup vs baseline: 1.0719x; 1.0719x over previous
#include <cuda_runtime.h>
#include <cuda_bf16.h>
#include <cstdint>

// ============================================================================
// out[65536,256] = (x[65536,512] @ W[256,512]^T) * 0.125 + 0.1*bias
// bf16 hi/lo 3-term split + mma.sync.m16n8k16 (base sm_103, no tcgen05).
// R9: warp-specialized (8 consumer + 4 producer warps, 3-stage mbarrier ring).
// Fix vs R8: producer covers FULL 128-row A tile (8 units/thread, not 4).
// ============================================================================

#define KD 512
#define ND 256
#define MROWS 65536
#define BM 128
#define BN 128
#define KB 32                 // k-cols per stage
#define NS 16                 // KD / KB
#define NPIPE 3
#define THREADS 384

// stage buffer (32KB): AHI 8K | ALO 8K | BHI 8K | BLO 8K
#define STAGE_BYTES 32768
#define BUF0 1024
#define SMEM_TOTAL (BUF0 + NPIPE * STAGE_BYTES)   // 99328

// mbarriers: full[j] at sb + j*8 ; empty[j] at sb + 24 + j*8

// ---- pre-split W: [stage 16][half 2][hi 8K | lo 8K], SW64 swizzled ----
__device__ __align__(1024) unsigned char g_w[16 * 2 * 2 * 8192];   // 512KB

__device__ __forceinline__ uint32_t swz64(uint32_t o) {
    return o ^ ((o >> 3) & 0x30);
}
__device__ __forceinline__ uint32_t smem_u32(const void* p) {
    uint32_t a;
    asm("{ .reg .u64 t; cvta.to.shared.u64 t, %1; cvt.u32.u64 %0, t; }"
        : "=r"(a) : "l"(p));
    return a;
}
__device__ __forceinline__ void sts64(uint32_t a, uint32_t r0, uint32_t r1) {
    asm volatile("st.shared.v2.b32 [%0], {%1,%2};" :: "r"(a), "r"(r0), "r"(r1)
                 : "memory");
}
// pack (lo arg -> low half, hi arg -> high half) as bf16x2
__device__ __forceinline__ uint32_t packbf(float lo, float hi) {
    uint32_t r;
    asm("cvt.rn.bf16x2.f32 %0, %1, %2;" : "=r"(r) : "f"(hi), "f"(lo));
    return r;
}

#define MBAR_INIT(a, c) \
    asm volatile("mbarrier.init.shared.b64 [%0], %1;" :: "r"(a), "r"(c) : "memory")
#define MBAR_EXPECT_TX(a, tx) \
    asm volatile("mbarrier.arrive.expect_tx.shared.b64 _, [%0], %1;" \
                 :: "r"(a), "r"(tx) : "memory")
#define MBAR_ARRIVE(a) \
    asm volatile("mbarrier.arrive.shared.b64 _, [%0];" :: "r"(a) : "memory")
#define MBAR_WAIT(a, par) do {                                              \
    asm volatile(                                                           \
        "{\n\t.reg .pred P1;\n\t"                                           \
        "WL_%=:\n\t"                                                        \
        "mbarrier.try_wait.parity.acquire.cta.shared::cta.b64 P1, [%0], %1, 0x989680;\n\t" \
        "@P1 bra.uni WD_%=;\n\t"                                            \
        "bra.uni WL_%=;\n\t"                                                \
        "WD_%=:\n\t}"                                                       \
        :: "r"(a), "r"(par) : "memory");                                    \
} while (0)

#define BULK_G2S(dst, src, sz, mbar) \
    asm volatile("cp.async.bulk.shared::cta.global.mbarrier::complete_tx::bytes " \
                 "[%0], [%1], %2, [%3];" \
                 :: "r"(dst), "l"(src), "r"(sz), "r"(mbar) : "memory")

#define LDSM4(r, addr) \
    asm volatile("ldmatrix.sync.aligned.m8n8.x4.shared.b16 {%0,%1,%2,%3}, [%4];" \
                 : "=r"((r)[0]), "=r"((r)[1]), "=r"((r)[2]), "=r"((r)[3])  \
                 : "r"(addr))

#define MMA(d, a, b0, b1) \
    asm volatile("mma.sync.aligned.m16n8k16.row.col.f32.bf16.bf16.f32 " \
                 "{%0,%1,%2,%3}, {%4,%5,%6,%7}, {%8,%9}, {%0,%1,%2,%3};" \
                 : "+f"((d)[0]), "+f"((d)[1]), "+f"((d)[2]), "+f"((d)[3]) \
                 : "r"((a)[0]), "r"((a)[1]), "r"((a)[2]), "r"((a)[3]),    \
                   "r"(b0), "r"(b1))

// ============================================================================
// W split: fp32 -> bf16 hi/lo into g_w[stage][half][hi|lo] (SW64 layout).
// ============================================================================
__global__ void split_w_kernel(const float* __restrict__ src) {
    const int n4 = ND * KD / 4;                       // 32768
    int i = blockIdx.x * blockDim.x + threadIdx.x;
    if (i >= n4) return;
    float4 v = ((const float4*)src)[i];
    int r = i >> 7;                // W row (n index) 0..255
    int c4 = i & 127;
    int s = c4 >> 3;               // k-stage
    int cc = c4 & 7;               // float4 within stage
    int h = r >> 7;                // n-half (BN block)
    int rl = r & 127;
    size_t base = ((size_t)(s * 2 + h) * 2) * 8192;
    uint32_t off = swz64((uint32_t)(rl * 64 + cc * 8));

    uint32_t h01 = packbf(v.x, v.y);
    uint32_t h23 = packbf(v.z, v.w);
    float lx = v.x - __uint_as_float(h01 << 16);
    float ly = v.y - __uint_as_float(h01 & 0xFFFF0000u);
    float lz = v.z - __uint_as_float(h23 << 16);
    float lw = v.w - __uint_as_float(h23 & 0xFFFF0000u);
    *(uint2*)(g_w + base + off) = make_uint2(h01, h23);
    *(uint2*)(g_w + base + 8192 + off) = make_uint2(packbf(lx, ly), packbf(lz, lw));
}

// ============================================================================
// Fused GEMM, warp-specialized
// ============================================================================
// producer A load: 8 float4/thread = full 128x32 fp32 tile across 128 threads
__device__ __forceinline__ void load_a(float4 pf[8], const float* x, int t,
                                       int bm, int ptid) {
#pragma unroll
    for (int j = 0; j < 8; j++) {
        const int idx = ptid + 128 * j;
        const int r = idx >> 3;          // 0..127
        const int c = idx & 7;           // float4 within 32-col stage
        pf[j] = *(const float4*)(x + (size_t)(bm + r) * KD + t * KB + c * 4);
    }
}

__device__ __forceinline__ void convert_sts(uint32_t buf, const float4 pf[8],
                                            int ptid) {
#pragma unroll
    for (int j = 0; j < 8; j++) {
        const int idx = ptid + 128 * j;
        const int r = idx >> 3;
        const int c = idx & 7;
        const uint32_t daddr = swz64((uint32_t)(r * 64 + c * 8));
        float4 v = pf[j];
        uint32_t h01 = packbf(v.x, v.y);
        uint32_t h23 = packbf(v.z, v.w);
        sts64(buf + daddr, h01, h23);
        uint32_t l01 = packbf(v.x - __uint_as_float(h01 << 16),
                              v.y - __uint_as_float(h01 & 0xFFFF0000u));
        uint32_t l23 = packbf(v.z - __uint_as_float(h23 << 16),
                              v.w - __uint_as_float(h23 & 0xFFFF0000u));
        sts64(buf + 8192 + daddr, l01, l23);
    }
}

__global__ void __launch_bounds__(THREADS, 1)
gemm_ws_kernel(const float* __restrict__ x, const float* __restrict__ bias,
               float* __restrict__ out) {
    extern __shared__ __align__(1024) char smem[];
    const uint32_t sb = smem_u32(smem);
    const int tid = threadIdx.x;
    const int wid = tid >> 5;
    const int lane = tid & 31;
    const int bn = blockIdx.x;     // fastest: bn pair adjacent (x L2 reuse)
    const int bm = blockIdx.y * BM;

    if (tid == 0) {
#pragma unroll
        for (int j = 0; j < NPIPE; j++) {
            MBAR_INIT(sb + j * 8, 129);        // full: 128 STS arrivals + expect_tx
            MBAR_INIT(sb + 24 + j * 8, 8);     // empty: 8 consumer warps
        }
        asm volatile("fence.proxy.async.shared::cta;" ::: "memory");
    }
    __syncthreads();

    if (wid >= 8) {
        // ================= PRODUCER (warps 8..11) =================
        const int ptid = tid - 256;
        float4 pf[2][8];
        load_a(pf[0], x, 0, bm, ptid);
        load_a(pf[1], x, 1, bm, ptid);

#pragma unroll 1
        for (int s = 0; s < NS; s++) {
            const int j = s % NPIPE;
            const int r = s / NPIPE;
            const uint32_t buf = sb + BUF0 + (uint32_t)j * STAGE_BYTES;
            if (r >= 1) MBAR_WAIT(sb + 24 + j * 8, (uint32_t)((r - 1) & 1));
            if (tid == 256) {
                MBAR_EXPECT_TX(sb + j * 8, 16384u);
                BULK_G2S(buf + 16384, g_w + (size_t)(s * 2 + bn) * 16384,
                         16384u, sb + j * 8);
            }
            convert_sts(buf, pf[s & 1], ptid);
            MBAR_ARRIVE(sb + j * 8);
            if (s + 2 < NS) load_a(pf[s & 1], x, s + 2, bm, ptid);
        }
        return;
    }

    // ================= CONSUMER (warps 0..7) =================
    const int wm = wid >> 2;       // 0..1, rows wm*64
    const int wn = wid & 3;        // 0..3, cols wn*32

    const int lrow8 = ((lane >> 3) & 1) * 8 + (lane & 7);
    const int lk16 = (lane >> 4) * 16;
    uint32_t aoff[4], boff[2];
#pragma unroll
    for (int mi = 0; mi < 4; mi++)
        aoff[mi] = (uint32_t)((wm * 64 + mi * 16 + lrow8) * 64 + lk16);
#pragma unroll
    for (int g = 0; g < 2; g++)
        boff[g] = (uint32_t)((wn * 32 + g * 16 + lrow8) * 64 + lk16);

    float acc[4][4][4];
#pragma unroll
    for (int mi = 0; mi < 4; mi++)
#pragma unroll
        for (int ni = 0; ni < 4; ni++)
#pragma unroll
            for (int j = 0; j < 4; j++) acc[mi][ni][j] = 0.0f;

#pragma unroll 1
    for (int s = 0; s < NS; s++) {
        const int j = s % NPIPE;
        const int r = s / NPIPE;
        MBAR_WAIT(sb + j * 8, (uint32_t)(r & 1));

        const uint32_t buf = sb + BUF0 + (uint32_t)j * STAGE_BYTES;
        const uint32_t ahi = buf, alo = buf + 8192;
        const uint32_t bhi = buf + 16384, blo = buf + 24576;

#pragma unroll
        for (int ks = 0; ks < 2; ks++) {
            const uint32_t kadd = (uint32_t)(ks * 32);
            uint32_t bht[2][4], blt[2][4];
#pragma unroll
            for (int g = 0; g < 2; g++) {
                LDSM4(bht[g], bhi + swz64(boff[g] + kadd));
                LDSM4(blt[g], blo + swz64(boff[g] + kadd));
            }
#pragma unroll
            for (int mi = 0; mi < 4; mi++) {
                uint32_t ah[4], al[4];
                LDSM4(ah, ahi + swz64(aoff[mi] + kadd));
                LDSM4(al, alo + swz64(aoff[mi] + kadd));
#pragma unroll
                for (int g = 0; g < 2; g++) {
                    MMA(acc[mi][2 * g],     ah, bht[g][0], bht[g][2]);
                    MMA(acc[mi][2 * g + 1], ah, bht[g][1], bht[g][3]);
                    MMA(acc[mi][2 * g],     ah, blt[g][0], blt[g][2]);
                    MMA(acc[mi][2 * g + 1], ah, blt[g][1], blt[g][3]);
                    MMA(acc[mi][2 * g],     al, bht[g][0], bht[g][2]);
                    MMA(acc[mi][2 * g + 1], al, bht[g][1], bht[g][3]);
                }
            }
        }
        if (lane == 0) MBAR_ARRIVE(sb + 24 + j * 8);
    }

    // ---- epilogue ----
    const int quad = lane >> 2;
    const int tq = lane & 3;
    const float scale = 0.125f;
#pragma unroll
    for (int mi = 0; mi < 4; mi++) {
        const int row0 = bm + wm * 64 + mi * 16 + quad;
#pragma unroll
        for (int ni = 0; ni < 4; ni++) {
            const int col = bn * BN + wn * 32 + ni * 8 + tq * 2;
            const float2 bv = *(const float2*)(bias + col);
            float2 o0, o1;
            o0.x = acc[mi][ni][0] * scale + 0.1f * bv.x;
            o0.y = acc[mi][ni][1] * scale + 0.1f * bv.y;
            o1.x = acc[mi][ni][2] * scale + 0.1f * bv.x;
            o1.y = acc[mi][ni][3] * scale + 0.1f * bv.y;
            *(float2*)(out + (size_t)row0 * ND + col) = o0;
            *(float2*)(out + (size_t)(row0 + 8) * ND + col) = o1;
        }
    }
}

// ============================================================================
extern "C" void kernel_launch(void* const* d_in, const int* in_sizes, int n_in,
                              void* d_out, int out_size) {
    const float* x      = (const float*)d_in[0];   // [65536, 512]
    const float* weight = (const float*)d_in[1];   // [256, 512]
    const float* bias   = (const float*)d_in[2];   // [256]
    float* out = (float*)d_out;                    // [65536, 256]

    cudaFuncSetAttribute(gemm_ws_kernel,
                         cudaFuncAttributeMaxDynamicSharedMemorySize, SMEM_TOTAL);

    split_w_kernel<<<128, 256>>>(weight);
    dim3 grid(ND / BN, MROWS / BM);   // (2, 512), bn fastest
    gemm_ws_kernel<<<grid, THREADS, SMEM_TOTAL>>>(x, bias, out);
}

// round 11
// speedup vs baseline: 2.0929x; 1.9524x over previous
#include <cuda_runtime.h>
#include <cuda_fp16.h>
#include <cstdint>

// ============================================================================
// out[65536,256] = (x[65536,512] @ W[256,512]^T) * 0.125 + 0.1*bias
// R10: SINGLE-TERM fp16 mma.sync.m16n8k16 (error ~4e-4 < 1e-3 threshold).
// Warp-specialized (8 consumer + 4 producer warps), 3-stage mbarrier ring,
// KB=64 (NS=8). 3x fewer MMAs than the bf16 hi/lo 3-term kernels.
// ============================================================================

#define KD 512
#define ND 256
#define MROWS 65536
#define BM 128
#define BN 128
#define KB 64                 // k-cols per stage (2 subchunks of 32)
#define NS 8                  // KD / KB
#define NPIPE 3
#define THREADS 384

// stage (32KB): A sub0 8K | A sub1 8K | B sub0 8K | B sub1 8K
#define STAGE_BYTES 32768
#define BUF0 1024
#define SMEM_TOTAL (BUF0 + NPIPE * STAGE_BYTES)   // 99328
// mbarriers: full[j] at sb + j*8 ; empty[j] at sb + 24 + j*8

// ---- pre-split W fp16: [half 2][kchunk 16] tiles of 8KB, SW64 swizzled ----
__device__ __align__(1024) unsigned char g_w[2 * 16 * 8192];   // 256KB

__device__ __forceinline__ uint32_t swz64(uint32_t o) {
    return o ^ ((o >> 3) & 0x30);
}
__device__ __forceinline__ uint32_t smem_u32(const void* p) {
    uint32_t a;
    asm("{ .reg .u64 t; cvta.to.shared.u64 t, %1; cvt.u32.u64 %0, t; }"
        : "=r"(a) : "l"(p));
    return a;
}
__device__ __forceinline__ void sts64(uint32_t a, uint32_t r0, uint32_t r1) {
    asm volatile("st.shared.v2.b32 [%0], {%1,%2};" :: "r"(a), "r"(r0), "r"(r1)
                 : "memory");
}
// pack (lo arg -> low half, hi arg -> high half) as f16x2
__device__ __forceinline__ uint32_t packf16(float lo, float hi) {
    uint32_t r;
    asm("cvt.rn.f16x2.f32 %0, %1, %2;" : "=r"(r) : "f"(hi), "f"(lo));
    return r;
}

#define MBAR_INIT(a, c) \
    asm volatile("mbarrier.init.shared.b64 [%0], %1;" :: "r"(a), "r"(c) : "memory")
#define MBAR_EXPECT_TX(a, tx) \
    asm volatile("mbarrier.arrive.expect_tx.shared.b64 _, [%0], %1;" \
                 :: "r"(a), "r"(tx) : "memory")
#define MBAR_ARRIVE(a) \
    asm volatile("mbarrier.arrive.shared.b64 _, [%0];" :: "r"(a) : "memory")
#define MBAR_WAIT(a, par) do {                                              \
    asm volatile(                                                           \
        "{\n\t.reg .pred P1;\n\t"                                           \
        "WL_%=:\n\t"                                                        \
        "mbarrier.try_wait.parity.acquire.cta.shared::cta.b64 P1, [%0], %1, 0x989680;\n\t" \
        "@P1 bra.uni WD_%=;\n\t"                                            \
        "bra.uni WL_%=;\n\t"                                                \
        "WD_%=:\n\t}"                                                       \
        :: "r"(a), "r"(par) : "memory");                                    \
} while (0)

#define BULK_G2S(dst, src, sz, mbar) \
    asm volatile("cp.async.bulk.shared::cta.global.mbarrier::complete_tx::bytes " \
                 "[%0], [%1], %2, [%3];" \
                 :: "r"(dst), "l"(src), "r"(sz), "r"(mbar) : "memory")

#define LDSM4(r, addr) \
    asm volatile("ldmatrix.sync.aligned.m8n8.x4.shared.b16 {%0,%1,%2,%3}, [%4];" \
                 : "=r"((r)[0]), "=r"((r)[1]), "=r"((r)[2]), "=r"((r)[3])  \
                 : "r"(addr))

#define MMA(d, a, b0, b1) \
    asm volatile("mma.sync.aligned.m16n8k16.row.col.f32.f16.f16.f32 " \
                 "{%0,%1,%2,%3}, {%4,%5,%6,%7}, {%8,%9}, {%0,%1,%2,%3};" \
                 : "+f"((d)[0]), "+f"((d)[1]), "+f"((d)[2]), "+f"((d)[3]) \
                 : "r"((a)[0]), "r"((a)[1]), "r"((a)[2]), "r"((a)[3]),    \
                   "r"(b0), "r"(b1))

// ============================================================================
// W split: fp32 -> fp16, layout g_w[half][kchunk] 8KB tiles (SW64 inside).
// ============================================================================
__global__ void split_w_kernel(const float* __restrict__ src) {
    const int n4 = ND * KD / 4;                       // 32768
    int i = blockIdx.x * blockDim.x + threadIdx.x;
    if (i >= n4) return;
    float4 v = ((const float4*)src)[i];
    int r = i >> 7;                // W row (n index) 0..255
    int c4 = i & 127;              // float4 within row
    int half = r >> 7;
    int rl = r & 127;
    int kchunk = c4 >> 3;          // 32-col chunk
    int cc = c4 & 7;
    size_t dstoff = (size_t)half * 131072 + (size_t)kchunk * 8192
                  + swz64((uint32_t)(rl * 64 + cc * 8));
    *(uint2*)(g_w + dstoff) = make_uint2(packf16(v.x, v.y), packf16(v.z, v.w));
}

// ============================================================================
// Fused GEMM, warp-specialized, single fp16 term
// ============================================================================
// producer A load: 16 float4/thread = full 128x64 fp32 tile across 128 threads
__device__ __forceinline__ void load_a(float4 pf[16], const float* x, int t,
                                       int bm, int ptid) {
#pragma unroll
    for (int j = 0; j < 16; j++) {
        const int u = ptid + 128 * j;
        const int r = u >> 4;            // 0..127
        const int c4 = u & 15;           // float4 within 64-col stage
        pf[j] = *(const float4*)(x + (size_t)(bm + r) * KD + t * KB + c4 * 4);
    }
}

__device__ __forceinline__ void convert_sts(uint32_t bufA, const float4 pf[16],
                                            int ptid) {
#pragma unroll
    for (int j = 0; j < 16; j++) {
        const int u = ptid + 128 * j;
        const int r = u >> 4;
        const int c4 = u & 15;
        const int kchunk = c4 >> 3;
        const int cc = c4 & 7;
        const uint32_t daddr = (uint32_t)(kchunk * 8192)
                             + swz64((uint32_t)(r * 64 + cc * 8));
        float4 v = pf[j];
        sts64(bufA + daddr, packf16(v.x, v.y), packf16(v.z, v.w));
    }
}

__global__ void __launch_bounds__(THREADS, 1)
gemm_ws_kernel(const float* __restrict__ x, const float* __restrict__ bias,
               float* __restrict__ out) {
    extern __shared__ __align__(1024) char smem[];
    const uint32_t sb = smem_u32(smem);
    const int tid = threadIdx.x;
    const int wid = tid >> 5;
    const int lane = tid & 31;
    const int bn = blockIdx.x;     // fastest: bn pair adjacent (x L2 reuse)
    const int bm = blockIdx.y * BM;

    if (tid == 0) {
#pragma unroll
        for (int j = 0; j < NPIPE; j++) {
            MBAR_INIT(sb + j * 8, 129);        // full: 128 STS arrivals + expect_tx
            MBAR_INIT(sb + 24 + j * 8, 8);     // empty: 8 consumer warps
        }
        asm volatile("fence.proxy.async.shared::cta;" ::: "memory");
    }
    __syncthreads();

    if (wid >= 8) {
        // ================= PRODUCER (warps 8..11) =================
        const int ptid = tid - 256;
        float4 pf[16];
        load_a(pf, x, 0, bm, ptid);

#pragma unroll 1
        for (int s = 0; s < NS; s++) {
            const int j = s % NPIPE;
            const int r = s / NPIPE;
            const uint32_t buf = sb + BUF0 + (uint32_t)j * STAGE_BYTES;
            if (r >= 1) MBAR_WAIT(sb + 24 + j * 8, (uint32_t)((r - 1) & 1));
            if (tid == 256) {
                MBAR_EXPECT_TX(sb + j * 8, 16384u);
                BULK_G2S(buf + 16384,
                         g_w + (size_t)bn * 131072 + (size_t)s * 16384,
                         16384u, sb + j * 8);
            }
            convert_sts(buf, pf, ptid);
            MBAR_ARRIVE(sb + j * 8);
            if (s + 1 < NS) load_a(pf, x, s + 1, bm, ptid);
        }
        return;
    }

    // ================= CONSUMER (warps 0..7) =================
    const int wm = wid >> 2;       // 0..1, rows wm*64
    const int wn = wid & 3;        // 0..3, cols wn*32

    const int lrow8 = ((lane >> 3) & 1) * 8 + (lane & 7);
    const int lk16 = (lane >> 4) * 16;
    uint32_t aoff[4], boff[2];
#pragma unroll
    for (int mi = 0; mi < 4; mi++)
        aoff[mi] = (uint32_t)((wm * 64 + mi * 16 + lrow8) * 64 + lk16);
#pragma unroll
    for (int g = 0; g < 2; g++)
        boff[g] = (uint32_t)((wn * 32 + g * 16 + lrow8) * 64 + lk16);

    float acc[4][4][4];
#pragma unroll
    for (int mi = 0; mi < 4; mi++)
#pragma unroll
        for (int ni = 0; ni < 4; ni++)
#pragma unroll
            for (int j = 0; j < 4; j++) acc[mi][ni][j] = 0.0f;

#pragma unroll 1
    for (int s = 0; s < NS; s++) {
        const int j = s % NPIPE;
        const int r = s / NPIPE;
        MBAR_WAIT(sb + j * 8, (uint32_t)(r & 1));

        const uint32_t bufA = sb + BUF0 + (uint32_t)j * STAGE_BYTES;
        const uint32_t bufB = bufA + 16384;

#pragma unroll
        for (int g4 = 0; g4 < 4; g4++) {           // 4 k16-groups
            const uint32_t sub = (uint32_t)((g4 >> 1) * 8192);
            const uint32_t kadd = (uint32_t)((g4 & 1) * 32);
            uint32_t bht[2][4];
#pragma unroll
            for (int g = 0; g < 2; g++)
                LDSM4(bht[g], bufB + sub + swz64(boff[g] + kadd));
#pragma unroll
            for (int mi = 0; mi < 4; mi++) {
                uint32_t ah[4];
                LDSM4(ah, bufA + sub + swz64(aoff[mi] + kadd));
#pragma unroll
                for (int g = 0; g < 2; g++) {
                    MMA(acc[mi][2 * g],     ah, bht[g][0], bht[g][2]);
                    MMA(acc[mi][2 * g + 1], ah, bht[g][1], bht[g][3]);
                }
            }
        }
        if (lane == 0) MBAR_ARRIVE(sb + 24 + j * 8);
    }

    // ---- epilogue ----
    const int quad = lane >> 2;
    const int tq = lane & 3;
    const float scale = 0.125f;
#pragma unroll
    for (int mi = 0; mi < 4; mi++) {
        const int row0 = bm + wm * 64 + mi * 16 + quad;
#pragma unroll
        for (int ni = 0; ni < 4; ni++) {
            const int col = bn * BN + wn * 32 + ni * 8 + tq * 2;
            const float2 bv = *(const float2*)(bias + col);
            float2 o0, o1;
            o0.x = acc[mi][ni][0] * scale + 0.1f * bv.x;
            o0.y = acc[mi][ni][1] * scale + 0.1f * bv.y;
            o1.x = acc[mi][ni][2] * scale + 0.1f * bv.x;
            o1.y = acc[mi][ni][3] * scale + 0.1f * bv.y;
            *(float2*)(out + (size_t)row0 * ND + col) = o0;
            *(float2*)(out + (size_t)(row0 + 8) * ND + col) = o1;
        }
    }
}

// ============================================================================
extern "C" void kernel_launch(void* const* d_in, const int* in_sizes, int n_in,
                              void* d_out, int out_size) {
    const float* x      = (const float*)d_in[0];   // [65536, 512]
    const float* weight = (const float*)d_in[1];   // [256, 512]
    const float* bias   = (const float*)d_in[2];   // [256]
    float* out = (float*)d_out;                    // [65536, 256]

    cudaFuncSetAttribute(gemm_ws_kernel,
                         cudaFuncAttributeMaxDynamicSharedMemorySize, SMEM_TOTAL);

    split_w_kernel<<<128, 256>>>(weight);
    dim3 grid(ND / BN, MROWS / BM);   // (2, 512), bn fastest
    gemm_ws_kernel<<<grid, THREADS, SMEM_TOTAL>>>(x, bias, out);
}

// round 12
// speedup vs baseline: 2.1351x; 1.0202x over previous
#include <cuda_runtime.h>
#include <cuda_fp16.h>
#include <cstdint>

// ============================================================================
// out[65536,256] = (x[65536,512] @ W[256,512]^T) * 0.125 + 0.1*bias
// R11: single-term fp16 mma.sync, warp-specialized (8 consumer + 4 producer),
// KB=128 (NS=4, NPIPE=2, 64KB stages) + explicit consumer fragment pipeline
// + producer batched streaming. Same mbarrier protocol as R10 (proven).
// ============================================================================

#define KD 512
#define ND 256
#define MROWS 65536
#define BM 128
#define BN 128
#define KB 128                // k-cols per stage (4 subchunks of 32)
#define NS 4                  // KD / KB
#define NPIPE 2
#define THREADS 384

// stage (64KB): A subchunks 4x8K | B subchunks 4x8K
#define STAGE_BYTES 65536
#define BUF0 1024
#define SMEM_TOTAL (BUF0 + NPIPE * STAGE_BYTES)   // 132096
// mbarriers: full[j] at sb + j*8 ; empty[j] at sb + 24 + j*8

// ---- pre-split W fp16: [half 2][kchunk 16] tiles of 8KB, SW64 swizzled ----
__device__ __align__(1024) unsigned char g_w[2 * 16 * 8192];   // 256KB

__device__ __forceinline__ uint32_t swz64(uint32_t o) {
    return o ^ ((o >> 3) & 0x30);
}
__device__ __forceinline__ uint32_t smem_u32(const void* p) {
    uint32_t a;
    asm("{ .reg .u64 t; cvta.to.shared.u64 t, %1; cvt.u32.u64 %0, t; }"
        : "=r"(a) : "l"(p));
    return a;
}
__device__ __forceinline__ void sts64(uint32_t a, uint32_t r0, uint32_t r1) {
    asm volatile("st.shared.v2.b32 [%0], {%1,%2};" :: "r"(a), "r"(r0), "r"(r1)
                 : "memory");
}
// pack (lo arg -> low half, hi arg -> high half) as f16x2
__device__ __forceinline__ uint32_t packf16(float lo, float hi) {
    uint32_t r;
    asm("cvt.rn.f16x2.f32 %0, %1, %2;" : "=r"(r) : "f"(hi), "f"(lo));
    return r;
}

#define MBAR_INIT(a, c) \
    asm volatile("mbarrier.init.shared.b64 [%0], %1;" :: "r"(a), "r"(c) : "memory")
#define MBAR_EXPECT_TX(a, tx) \
    asm volatile("mbarrier.arrive.expect_tx.shared.b64 _, [%0], %1;" \
                 :: "r"(a), "r"(tx) : "memory")
#define MBAR_ARRIVE(a) \
    asm volatile("mbarrier.arrive.shared.b64 _, [%0];" :: "r"(a) : "memory")
#define MBAR_WAIT(a, par) do {                                              \
    asm volatile(                                                           \
        "{\n\t.reg .pred P1;\n\t"                                           \
        "WL_%=:\n\t"                                                        \
        "mbarrier.try_wait.parity.acquire.cta.shared::cta.b64 P1, [%0], %1, 0x989680;\n\t" \
        "@P1 bra.uni WD_%=;\n\t"                                            \
        "bra.uni WL_%=;\n\t"                                                \
        "WD_%=:\n\t}"                                                       \
        :: "r"(a), "r"(par) : "memory");                                    \
} while (0)

#define BULK_G2S(dst, src, sz, mbar) \
    asm volatile("cp.async.bulk.shared::cta.global.mbarrier::complete_tx::bytes " \
                 "[%0], [%1], %2, [%3];" \
                 :: "r"(dst), "l"(src), "r"(sz), "r"(mbar) : "memory")

#define LDSM4(r, addr) \
    asm volatile("ldmatrix.sync.aligned.m8n8.x4.shared.b16 {%0,%1,%2,%3}, [%4];" \
                 : "=r"((r)[0]), "=r"((r)[1]), "=r"((r)[2]), "=r"((r)[3])  \
                 : "r"(addr))

#define MMA(d, a, b0, b1) \
    asm volatile("mma.sync.aligned.m16n8k16.row.col.f32.f16.f16.f32 " \
                 "{%0,%1,%2,%3}, {%4,%5,%6,%7}, {%8,%9}, {%0,%1,%2,%3};" \
                 : "+f"((d)[0]), "+f"((d)[1]), "+f"((d)[2]), "+f"((d)[3]) \
                 : "r"((a)[0]), "r"((a)[1]), "r"((a)[2]), "r"((a)[3]),    \
                   "r"(b0), "r"(b1))

// ============================================================================
// W split: fp32 -> fp16, layout g_w[half][kchunk] 8KB tiles (SW64 inside).
// ============================================================================
__global__ void split_w_kernel(const float* __restrict__ src) {
    const int n4 = ND * KD / 4;                       // 32768
    int i = blockIdx.x * blockDim.x + threadIdx.x;
    if (i >= n4) return;
    float4 v = ((const float4*)src)[i];
    int r = i >> 7;                // W row (n index) 0..255
    int c4 = i & 127;              // float4 within row
    int half = r >> 7;
    int rl = r & 127;
    int kchunk = c4 >> 3;          // 32-col chunk
    int cc = c4 & 7;
    size_t dstoff = (size_t)half * 131072 + (size_t)kchunk * 8192
                  + swz64((uint32_t)(rl * 64 + cc * 8));
    *(uint2*)(g_w + dstoff) = make_uint2(packf16(v.x, v.y), packf16(v.z, v.w));
}

// ============================================================================
// Fused GEMM, warp-specialized, single fp16 term
// ============================================================================
// producer batch load: 8 float4/thread, batch b covers rows 32b..32b+31
__device__ __forceinline__ void load_batch(float4 pf[8], const float* x, int t,
                                           int bm, int ptid, int b) {
#pragma unroll
    for (int j = 0; j < 8; j++) {
        const int u = ptid + 128 * (8 * b + j);
        const int r = u >> 5;            // row 0..127
        const int c4 = u & 31;           // float4 within 128-col stage
        pf[j] = *(const float4*)(x + (size_t)(bm + r) * KD + t * KB + c4 * 4);
    }
}

__device__ __forceinline__ void cvt_sts_batch(uint32_t bufA, const float4 pf[8],
                                              int ptid, int b) {
#pragma unroll
    for (int j = 0; j < 8; j++) {
        const int u = ptid + 128 * (8 * b + j);
        const int r = u >> 5;
        const int c4 = u & 31;
        const uint32_t daddr = (uint32_t)((c4 >> 3) * 8192)
                             + swz64((uint32_t)(r * 64 + (c4 & 7) * 8));
        float4 v = pf[j];
        sts64(bufA + daddr, packf16(v.x, v.y), packf16(v.z, v.w));
    }
}

__global__ void __launch_bounds__(THREADS, 1)
gemm_ws_kernel(const float* __restrict__ x, const float* __restrict__ bias,
               float* __restrict__ out) {
    extern __shared__ __align__(1024) char smem[];
    const uint32_t sb = smem_u32(smem);
    const int tid = threadIdx.x;
    const int wid = tid >> 5;
    const int lane = tid & 31;
    const int bn = blockIdx.x;     // fastest: bn pair adjacent (x L2 reuse)
    const int bm = blockIdx.y * BM;

    if (tid == 0) {
#pragma unroll
        for (int j = 0; j < NPIPE; j++) {
            MBAR_INIT(sb + j * 8, 129);        // full: 128 STS arrivals + expect_tx
            MBAR_INIT(sb + 24 + j * 8, 8);     // empty: 8 consumer warps
        }
        asm volatile("fence.proxy.async.shared::cta;" ::: "memory");
    }
    __syncthreads();

    if (wid >= 8) {
        // ================= PRODUCER (warps 8..11) =================
        const int ptid = tid - 256;
        float4 pf[2][8];

#pragma unroll 1
        for (int s = 0; s < NS; s++) {
            const int j = s & 1;
            const int r = s >> 1;
            const uint32_t buf = sb + BUF0 + (uint32_t)j * STAGE_BYTES;
            if (r >= 1) MBAR_WAIT(sb + 24 + j * 8, (uint32_t)((r - 1) & 1));
            if (tid == 256) {
                MBAR_EXPECT_TX(sb + j * 8, 32768u);
                BULK_G2S(buf + 32768,
                         g_w + (size_t)bn * 131072 + (size_t)s * 32768,
                         32768u, sb + j * 8);
            }
            // 4 ping-pong batches of 8 float4
            load_batch(pf[0], x, s, bm, ptid, 0);
#pragma unroll
            for (int b = 0; b < 4; b++) {
                if (b < 3) load_batch(pf[(b + 1) & 1], x, s, bm, ptid, b + 1);
                cvt_sts_batch(buf, pf[b & 1], ptid, b);
            }
            MBAR_ARRIVE(sb + j * 8);
        }
        return;
    }

    // ================= CONSUMER (warps 0..7) =================
    const int wm = wid >> 2;       // 0..1, rows wm*64
    const int wn = wid & 3;        // 0..3, cols wn*32

    const int lrow8 = ((lane >> 3) & 1) * 8 + (lane & 7);
    const int lk16 = (lane >> 4) * 16;
    uint32_t aoff[4], boff[2];
#pragma unroll
    for (int mi = 0; mi < 4; mi++)
        aoff[mi] = (uint32_t)((wm * 64 + mi * 16 + lrow8) * 64 + lk16);
#pragma unroll
    for (int g = 0; g < 2; g++)
        boff[g] = (uint32_t)((wn * 32 + g * 16 + lrow8) * 64 + lk16);

    float acc[4][4][4];
#pragma unroll
    for (int mi = 0; mi < 4; mi++)
#pragma unroll
        for (int ni = 0; ni < 4; ni++)
#pragma unroll
            for (int j = 0; j < 4; j++) acc[mi][ni][j] = 0.0f;

    // double-buffered fragment sets: [buf][...]
    uint32_t bht[2][2][4];
    uint32_t ahh[2][4][4];

#pragma unroll 1
    for (int s = 0; s < NS; s++) {
        const int j = s & 1;
        const int r = s >> 1;
        MBAR_WAIT(sb + j * 8, (uint32_t)(r & 1));

        const uint32_t bufA = sb + BUF0 + (uint32_t)j * STAGE_BYTES;
        const uint32_t bufB = bufA + 32768;

        // prefetch group 0 fragments
        {
            const uint32_t sub = 0, kadd = 0;
#pragma unroll
            for (int g = 0; g < 2; g++)
                LDSM4(bht[0][g], bufB + sub + swz64(boff[g] + kadd));
#pragma unroll
            for (int mi = 0; mi < 4; mi++)
                LDSM4(ahh[0][mi], bufA + sub + swz64(aoff[mi] + kadd));
        }

#pragma unroll
        for (int g4 = 0; g4 < 8; g4++) {           // 8 k16-groups
            const int cb = g4 & 1;
            // prefetch next group's fragments BEFORE this group's MMAs
            if (g4 < 7) {
                const int gn = g4 + 1;
                const uint32_t sub = (uint32_t)((gn >> 1) * 8192);
                const uint32_t kadd = (uint32_t)((gn & 1) * 32);
                const int nb = gn & 1;
#pragma unroll
                for (int g = 0; g < 2; g++)
                    LDSM4(bht[nb][g], bufB + sub + swz64(boff[g] + kadd));
#pragma unroll
                for (int mi = 0; mi < 4; mi++)
                    LDSM4(ahh[nb][mi], bufA + sub + swz64(aoff[mi] + kadd));
            }
#pragma unroll
            for (int mi = 0; mi < 4; mi++) {
#pragma unroll
                for (int g = 0; g < 2; g++) {
                    MMA(acc[mi][2 * g],     ahh[cb][mi], bht[cb][g][0], bht[cb][g][2]);
                    MMA(acc[mi][2 * g + 1], ahh[cb][mi], bht[cb][g][1], bht[cb][g][3]);
                }
            }
        }
        if (lane == 0) MBAR_ARRIVE(sb + 24 + j * 8);
    }

    // ---- epilogue ----
    const int quad = lane >> 2;
    const int tq = lane & 3;
    const float scale = 0.125f;
#pragma unroll
    for (int mi = 0; mi < 4; mi++) {
        const int row0 = bm + wm * 64 + mi * 16 + quad;
#pragma unroll
        for (int ni = 0; ni < 4; ni++) {
            const int col = bn * BN + wn * 32 + ni * 8 + tq * 2;
            const float2 bv = *(const float2*)(bias + col);
            float2 o0, o1;
            o0.x = acc[mi][ni][0] * scale + 0.1f * bv.x;
            o0.y = acc[mi][ni][1] * scale + 0.1f * bv.y;
            o1.x = acc[mi][ni][2] * scale + 0.1f * bv.x;
            o1.y = acc[mi][ni][3] * scale + 0.1f * bv.y;
            *(float2*)(out + (size_t)row0 * ND + col) = o0;
            *(float2*)(out + (size_t)(row0 + 8) * ND + col) = o1;
        }
    }
}

// ============================================================================
extern "C" void kernel_launch(void* const* d_in, const int* in_sizes, int n_in,
                              void* d_out, int out_size) {
    const float* x      = (const float*)d_in[0];   // [65536, 512]
    const float* weight = (const float*)d_in[1];   // [256, 512]
    const float* bias   = (const float*)d_in[2];   // [256]
    float* out = (float*)d_out;                    // [65536, 256]

    cudaFuncSetAttribute(gemm_ws_kernel,
                         cudaFuncAttributeMaxDynamicSharedMemorySize, SMEM_TOTAL);

    split_w_kernel<<<128, 256>>>(weight);
    dim3 grid(ND / BN, MROWS / BM);   // (2, 512), bn fastest
    gemm_ws_kernel<<<grid, THREADS, SMEM_TOTAL>>>(x, bias, out);
}